// round 1
// baseline (speedup 1.0000x reference)
#include <cuda_runtime.h>
#include <cuda_fp16.h>
#include <cstdint>

// Problem dims
#define TT 256
#define BB 128
#define EE 1024
#define HH 1024
#define N4 4096   // 4*H, gate-interleaved: n' = j*4 + gate  (gate: 0=g,1=i,2=f,3=o)

// ---------------- device scratch (allocation-free: __device__ globals) ----------------
__device__ __half g_Wx[N4 * EE];                       // 8 MB   W[:, :E]  reordered
__device__ __half g_Wh[N4 * HH];                       // 8 MB   W[:, E:]  reordered
__device__ float  g_bias[N4];                          // reordered bias
__device__ __half g_X16[(TT - 1) * BB * EE];           // 66.8 MB, embeds[1:] in fp16
__device__ float  g_Zx[(TT - 1) * BB * N4];            // 535 MB, x-part preactivations (+bias)
__device__ float  g_c[BB * HH];                        // cell state
__device__ __half g_h16[BB * HH];                      // h state (fp16 for next GEMM)

// ---------------- helpers ----------------
__device__ __forceinline__ void mma16816(float* d, const uint32_t* a, const uint32_t* b) {
    asm volatile(
        "mma.sync.aligned.m16n8k16.row.col.f32.f16.f16.f32 "
        "{%0,%1,%2,%3}, {%4,%5,%6,%7}, {%8,%9}, {%0,%1,%2,%3};\n"
        : "+f"(d[0]), "+f"(d[1]), "+f"(d[2]), "+f"(d[3])
        : "r"(a[0]), "r"(a[1]), "r"(a[2]), "r"(a[3]), "r"(b[0]), "r"(b[1]));
}

__device__ __forceinline__ float sigmoidf_(float x) { return 1.0f / (1.0f + expf(-x)); }

// ---------------- conversion / init kernels ----------------
__global__ void convw_kernel(const float* __restrict__ Wg, const float* __restrict__ Wi,
                             const float* __restrict__ Wf, const float* __restrict__ Wo,
                             const float* __restrict__ bg, const float* __restrict__ bi,
                             const float* __restrict__ bf, const float* __restrict__ bo) {
    int idx = blockIdx.x * 256 + threadIdx.x;            // over N4*1024
    if (idx >= N4 * 1024) return;
    int np = idx >> 10, k = idx & 1023;
    int j = np >> 2, gate = np & 3;
    const float* W = (gate == 0) ? Wg : (gate == 1) ? Wi : (gate == 2) ? Wf : Wo;
    g_Wx[idx] = __float2half(W[j * 2048 + k]);
    g_Wh[idx] = __float2half(W[j * 2048 + 1024 + k]);
    if (k == 0) {
        const float* bs = (gate == 0) ? bg : (gate == 1) ? bi : (gate == 2) ? bf : bo;
        g_bias[np] = bs[j];
    }
}

__global__ void convx_kernel(const float* __restrict__ embeds) {
    int i = blockIdx.x * 256 + threadIdx.x;
    if (i < (TT - 1) * BB * EE) g_X16[i] = __float2half(embeds[i + BB * EE]);
}

__global__ void init_kernel(float* __restrict__ out) {
    int i = blockIdx.x * 256 + threadIdx.x;
    if (i < BB * HH) {
        g_c[i] = 0.0f;
        g_h16[i] = __float2half(0.0f);
        out[i] = 0.0f;                                   // out[0] = h0 = zeros
    }
}

// ---------------- x-GEMM: Zx[m][n'] = bias[n'] + X[m] . Wx[n']  ----------------
// BM=128, BN=64, BK=64; 256 threads; 8 warps as 4(M) x 2(N); warp tile 32x32.
__global__ void xgemm_kernel() {
    __shared__ __align__(16) __half As[128 * 72];
    __shared__ __align__(16) __half Bs[64 * 72];
    const int bx = blockIdx.x;                 // n tile (64 tiles of 64)
    const int by = blockIdx.y;                 // m tile (255 tiles of 128)
    const int tid = threadIdx.x;
    const int warp = tid >> 5, lane = tid & 31;
    const int wm = warp & 3, wn = warp >> 2;
    const int group = lane >> 2, tq = lane & 3;

    const __half* Ag = g_X16 + (size_t)by * 128 * 1024;
    const __half* Bg = g_Wx + (size_t)bx * 64 * 1024;

    float acc[2][4][4];
#pragma unroll
    for (int mt = 0; mt < 2; mt++)
#pragma unroll
        for (int nt = 0; nt < 4; nt++)
#pragma unroll
            for (int e = 0; e < 4; e++) acc[mt][nt][e] = 0.0f;

    for (int k0 = 0; k0 < 1024; k0 += 64) {
#pragma unroll
        for (int i = 0; i < 4; i++) {          // A: 1024 uint4
            int idx = tid + i * 256;
            int r = idx >> 3, c = idx & 7;
            *(uint4*)&As[r * 72 + c * 8] = *(const uint4*)&Ag[r * 1024 + k0 + c * 8];
        }
#pragma unroll
        for (int i = 0; i < 2; i++) {          // B: 512 uint4
            int idx = tid + i * 256;
            int r = idx >> 3, c = idx & 7;
            *(uint4*)&Bs[r * 72 + c * 8] = *(const uint4*)&Bg[r * 1024 + k0 + c * 8];
        }
        __syncthreads();
#pragma unroll
        for (int kk = 0; kk < 64; kk += 16) {
            uint32_t af[2][4], bf[4][2];
#pragma unroll
            for (int mt = 0; mt < 2; mt++) {
                int ra = wm * 32 + mt * 16;
                af[mt][0] = *(const uint32_t*)&As[(ra + group) * 72 + kk + tq * 2];
                af[mt][1] = *(const uint32_t*)&As[(ra + group + 8) * 72 + kk + tq * 2];
                af[mt][2] = *(const uint32_t*)&As[(ra + group) * 72 + kk + 8 + tq * 2];
                af[mt][3] = *(const uint32_t*)&As[(ra + group + 8) * 72 + kk + 8 + tq * 2];
            }
#pragma unroll
            for (int nt = 0; nt < 4; nt++) {
                int rb = wn * 32 + nt * 8;
                bf[nt][0] = *(const uint32_t*)&Bs[(rb + group) * 72 + kk + tq * 2];
                bf[nt][1] = *(const uint32_t*)&Bs[(rb + group) * 72 + kk + 8 + tq * 2];
            }
#pragma unroll
            for (int mt = 0; mt < 2; mt++)
#pragma unroll
                for (int nt = 0; nt < 4; nt++) mma16816(acc[mt][nt], af[mt], bf[nt]);
        }
        __syncthreads();
    }
    // store with bias
#pragma unroll
    for (int mt = 0; mt < 2; mt++) {
#pragma unroll
        for (int nt = 0; nt < 4; nt++) {
            int r0 = wm * 32 + mt * 16 + group;
            int c0 = wn * 32 + nt * 8 + tq * 2;
            int m0 = by * 128;
            int n0 = bx * 64;
            float* o0 = &g_Zx[(size_t)(m0 + r0) * 4096 + n0 + c0];
            o0[0] = acc[mt][nt][0] + g_bias[n0 + c0];
            o0[1] = acc[mt][nt][1] + g_bias[n0 + c0 + 1];
            float* o1 = &g_Zx[(size_t)(m0 + r0 + 8) * 4096 + n0 + c0];
            o1[0] = acc[mt][nt][2] + g_bias[n0 + c0];
            o1[1] = acc[mt][nt][3] + g_bias[n0 + c0 + 1];
        }
    }
}

// ---------------- fused recurrent step ----------------
// One kernel per t: z = Zx[t] + h_prev @ Wh^T, gates, c/h update.
// Grid: 128 CTAs (N tiles of 32, gate-interleaved so each tile holds 8 full j's).
// BM=128(all of B), BN=32, BK=64; 256 threads; warps 4(M) x 2(N); warp tile 32x16.
__global__ void step_kernel(float* __restrict__ out, int t) {
    __shared__ __align__(16) __half As[128 * 72];
    __shared__ __align__(16) __half Bs[32 * 72];
    __shared__ __align__(16) float zbuf[128 * 36];
    const int bx = blockIdx.x;                 // n tile (128 tiles of 32)
    const int tid = threadIdx.x;
    const int warp = tid >> 5, lane = tid & 31;
    const int wm = warp & 3, wn = warp >> 2;
    const int group = lane >> 2, tq = lane & 3;

    const __half* Bg = g_Wh + (size_t)bx * 32 * 1024;

    float acc[2][2][4];
#pragma unroll
    for (int mt = 0; mt < 2; mt++)
#pragma unroll
        for (int nt = 0; nt < 2; nt++)
#pragma unroll
            for (int e = 0; e < 4; e++) acc[mt][nt][e] = 0.0f;

    for (int k0 = 0; k0 < 1024; k0 += 64) {
#pragma unroll
        for (int i = 0; i < 4; i++) {          // A = h_prev (fp16), 128x64 chunk
            int idx = tid + i * 256;
            int r = idx >> 3, c = idx & 7;
            *(uint4*)&As[r * 72 + c * 8] = *(const uint4*)&g_h16[r * 1024 + k0 + c * 8];
        }
        {                                      // B = Wh tile, 32x64 chunk
            int r = tid >> 3, c = tid & 7;
            *(uint4*)&Bs[r * 72 + c * 8] = *(const uint4*)&Bg[r * 1024 + k0 + c * 8];
        }
        __syncthreads();
#pragma unroll
        for (int kk = 0; kk < 64; kk += 16) {
            uint32_t af[2][4], bf[2][2];
#pragma unroll
            for (int mt = 0; mt < 2; mt++) {
                int ra = wm * 32 + mt * 16;
                af[mt][0] = *(const uint32_t*)&As[(ra + group) * 72 + kk + tq * 2];
                af[mt][1] = *(const uint32_t*)&As[(ra + group + 8) * 72 + kk + tq * 2];
                af[mt][2] = *(const uint32_t*)&As[(ra + group) * 72 + kk + 8 + tq * 2];
                af[mt][3] = *(const uint32_t*)&As[(ra + group + 8) * 72 + kk + 8 + tq * 2];
            }
#pragma unroll
            for (int nt = 0; nt < 2; nt++) {
                int rb = wn * 16 + nt * 8;
                bf[nt][0] = *(const uint32_t*)&Bs[(rb + group) * 72 + kk + tq * 2];
                bf[nt][1] = *(const uint32_t*)&Bs[(rb + group) * 72 + kk + 8 + tq * 2];
            }
#pragma unroll
            for (int mt = 0; mt < 2; mt++)
#pragma unroll
                for (int nt = 0; nt < 2; nt++) mma16816(acc[mt][nt], af[mt], bf[nt]);
        }
        __syncthreads();
    }

    // spill z tile (h.Wh part) to smem
#pragma unroll
    for (int mt = 0; mt < 2; mt++) {
#pragma unroll
        for (int nt = 0; nt < 2; nt++) {
            int r0 = wm * 32 + mt * 16 + group;
            int c0 = wn * 16 + nt * 8 + tq * 2;
            zbuf[r0 * 36 + c0]       = acc[mt][nt][0];
            zbuf[r0 * 36 + c0 + 1]   = acc[mt][nt][1];
            zbuf[(r0 + 8) * 36 + c0]     = acc[mt][nt][2];
            zbuf[(r0 + 8) * 36 + c0 + 1] = acc[mt][nt][3];
        }
    }
    __syncthreads();

    // combine: 1024 (b, j) pairs in this tile, 4 per thread
    const float* Zxt = g_Zx + (size_t)(t - 1) * BB * N4;
#pragma unroll
    for (int i = 0; i < 4; i++) {
        int p = tid + i * 256;                  // 0..1023
        int b = p >> 3, jl = p & 7;
        float4 zh = *(const float4*)&zbuf[b * 36 + jl * 4];
        float4 zx = *(const float4*)&Zxt[(size_t)b * 4096 + bx * 32 + jl * 4];
        float zg = zh.x + zx.x;
        float zi = zh.y + zx.y;
        float zf = zh.z + zx.z;
        float zo = zh.w + zx.w;
        float gg = tanhf(zg);
        float ii = sigmoidf_(zi);
        float ff = sigmoidf_(zf);
        float oo = sigmoidf_(zo);
        int jg = bx * 8 + jl;
        int ci = b * 1024 + jg;
        float cn = ff * g_c[ci] + ii * gg;
        float hn = oo * tanhf(cn);
        g_c[ci] = cn;
        out[(size_t)t * (BB * HH) + ci] = hn;
        g_h16[ci] = __float2half(hn);
    }
}

// ---------------- launch ----------------
extern "C" void kernel_launch(void* const* d_in, const int* in_sizes, int n_in,
                              void* d_out, int out_size) {
    const float* embeds = (const float*)d_in[0];
    const float* Wg = (const float*)d_in[1];
    const float* Wi = (const float*)d_in[2];
    const float* Wf = (const float*)d_in[3];
    const float* Wo = (const float*)d_in[4];
    const float* bg = (const float*)d_in[5];
    const float* bi = (const float*)d_in[6];
    const float* bf = (const float*)d_in[7];
    const float* bo = (const float*)d_in[8];
    float* out = (float*)d_out;

    convw_kernel<<<(N4 * 1024 + 255) / 256, 256>>>(Wg, Wi, Wf, Wo, bg, bi, bf, bo);
    convx_kernel<<<((TT - 1) * BB * EE + 255) / 256, 256>>>(embeds);
    init_kernel<<<(BB * HH + 255) / 256, 256>>>(out);

    dim3 gx(64, TT - 1);
    xgemm_kernel<<<gx, 256>>>();

    for (int t = 1; t < TT; t++) {
        step_kernel<<<128, 256>>>(out, t);
    }
}

// round 2
// speedup vs baseline: 1.5938x; 1.5938x over previous
#include <cuda_runtime.h>
#include <cuda_fp16.h>
#include <cstdint>

// Problem dims
#define TT 256
#define BB 128
#define EE 1024
#define HH 1024
#define N4 4096   // 4*H, gate-interleaved: n' = j*4 + gate  (0=g,1=i,2=f,3=o)
#define NCTA 128  // persistent kernel CTAs (all co-resident: 128 <= 148 SMs)

// ---------------- device scratch (allocation-free: __device__ globals) ----------------
__device__ __half g_Wx[N4 * EE];                       // 8 MB   W[:, :E]  reordered
__device__ __half g_Wh[N4 * HH];                       // 8 MB   W[:, E:]  reordered
__device__ float  g_bias[N4];                          // reordered bias
__device__ __half g_X16[(TT - 1) * BB * EE];           // 66.8 MB, embeds[1:] fp16
__device__ float  g_Zx[(TT - 1) * BB * N4];            // 535 MB, x-part preactivations (+bias)
__device__ __half g_h2[2 * BB * HH];                   // double-buffered h (fp16)
__device__ unsigned g_bar;                             // grid barrier counter

// ---------------- helpers ----------------
__device__ __forceinline__ void mma16816(float* d, const uint32_t* a, const uint32_t* b) {
    asm volatile(
        "mma.sync.aligned.m16n8k16.row.col.f32.f16.f16.f32 "
        "{%0,%1,%2,%3}, {%4,%5,%6,%7}, {%8,%9}, {%0,%1,%2,%3};\n"
        : "+f"(d[0]), "+f"(d[1]), "+f"(d[2]), "+f"(d[3])
        : "r"(a[0]), "r"(a[1]), "r"(a[2]), "r"(a[3]), "r"(b[0]), "r"(b[1]));
}

__device__ __forceinline__ void ldsm_x4(uint32_t& r0, uint32_t& r1, uint32_t& r2, uint32_t& r3,
                                        uint32_t addr) {
    asm volatile("ldmatrix.sync.aligned.m8n8.x4.shared.b16 {%0,%1,%2,%3}, [%4];\n"
                 : "=r"(r0), "=r"(r1), "=r"(r2), "=r"(r3) : "r"(addr));
}

__device__ __forceinline__ void cpasync16(uint32_t saddr, const void* g) {
    asm volatile("cp.async.cg.shared.global [%0], [%1], 16;\n" :: "r"(saddr), "l"(g));
}
__device__ __forceinline__ void cp_commit() { asm volatile("cp.async.commit_group;\n"); }
template <int N>
__device__ __forceinline__ void cp_wait() { asm volatile("cp.async.wait_group %0;\n" :: "n"(N)); }

__device__ __forceinline__ float sigmoidf_(float x) { return 1.0f / (1.0f + expf(-x)); }

// ---------------- conversion / init kernels ----------------
__global__ void convw_kernel(const float* __restrict__ Wg, const float* __restrict__ Wi,
                             const float* __restrict__ Wf, const float* __restrict__ Wo,
                             const float* __restrict__ bg, const float* __restrict__ bi,
                             const float* __restrict__ bf, const float* __restrict__ bo) {
    int idx = blockIdx.x * 256 + threadIdx.x;            // over N4*1024
    if (idx >= N4 * 1024) return;
    int np = idx >> 10, k = idx & 1023;
    int j = np >> 2, gate = np & 3;
    const float* W = (gate == 0) ? Wg : (gate == 1) ? Wi : (gate == 2) ? Wf : Wo;
    g_Wx[idx] = __float2half(W[j * 2048 + k]);
    g_Wh[idx] = __float2half(W[j * 2048 + 1024 + k]);
    if (k == 0) {
        const float* bs = (gate == 0) ? bg : (gate == 1) ? bi : (gate == 2) ? bf : bo;
        g_bias[np] = bs[j];
    }
}

__global__ void convx_kernel(const float* __restrict__ embeds) {
    int i = blockIdx.x * 256 + threadIdx.x;
    if (i < (TT - 1) * BB * EE) g_X16[i] = __float2half(embeds[i + BB * EE]);
}

__global__ void init_kernel() {
    if (threadIdx.x == 0) g_bar = 0u;                    // reset barrier per graph replay
}

// ---------------- x-GEMM: Zx[m][n'] = bias[n'] + X[m] . Wx[n'] ----------------
// BM=128, BN=64, BK=64; 256 threads; 8 warps as 4(M) x 2(N); warp tile 32x32.
__global__ void xgemm_kernel() {
    __shared__ __align__(16) __half As[128 * 72];
    __shared__ __align__(16) __half Bs[64 * 72];
    const int bx = blockIdx.x;                 // n tile (64 tiles of 64)
    const int by = blockIdx.y;                 // m tile (255 tiles of 128)
    const int tid = threadIdx.x;
    const int warp = tid >> 5, lane = tid & 31;
    const int wm = warp & 3, wn = warp >> 2;
    const int group = lane >> 2, tq = lane & 3;

    const __half* Ag = g_X16 + (size_t)by * 128 * 1024;
    const __half* Bg = g_Wx + (size_t)bx * 64 * 1024;

    uint32_t as_u = (uint32_t)__cvta_generic_to_shared(As);
    uint32_t bs_u = (uint32_t)__cvta_generic_to_shared(Bs);

    // precomputed ldmatrix byte offsets (k term added in loop)
    uint32_t a_off[2], b_off[2];
#pragma unroll
    for (int mt = 0; mt < 2; mt++)
        a_off[mt] = as_u + ((wm * 32 + mt * 16 + (lane & 15)) * 72 + ((lane >> 4) << 3)) * 2;
    {
        int m = lane >> 3;
#pragma unroll
        for (int p = 0; p < 2; p++)
            b_off[p] = bs_u + ((wn * 32 + p * 16 + ((m >> 1) << 3) + (lane & 7)) * 72 +
                               ((m & 1) << 3)) * 2;
    }

    float acc[2][4][4];
#pragma unroll
    for (int mt = 0; mt < 2; mt++)
#pragma unroll
        for (int nt = 0; nt < 4; nt++)
#pragma unroll
            for (int e = 0; e < 4; e++) acc[mt][nt][e] = 0.0f;

    for (int k0 = 0; k0 < 1024; k0 += 64) {
#pragma unroll
        for (int i = 0; i < 4; i++) {          // A: 1024 x 16B
            int idx = tid + i * 256;
            int r = idx >> 3, c = idx & 7;
            cpasync16(as_u + (r * 72 + c * 8) * 2, &Ag[r * 1024 + k0 + c * 8]);
        }
#pragma unroll
        for (int i = 0; i < 2; i++) {          // B: 512 x 16B
            int idx = tid + i * 256;
            int r = idx >> 3, c = idx & 7;
            cpasync16(bs_u + (r * 72 + c * 8) * 2, &Bg[r * 1024 + k0 + c * 8]);
        }
        cp_commit();
        cp_wait<0>();
        __syncthreads();
#pragma unroll
        for (int kk = 0; kk < 64; kk += 16) {
            uint32_t af[2][4], bf[4][2];
#pragma unroll
            for (int mt = 0; mt < 2; mt++)
                ldsm_x4(af[mt][0], af[mt][1], af[mt][2], af[mt][3], a_off[mt] + kk * 2);
#pragma unroll
            for (int p = 0; p < 2; p++)
                ldsm_x4(bf[2 * p][0], bf[2 * p][1], bf[2 * p + 1][0], bf[2 * p + 1][1],
                        b_off[p] + kk * 2);
#pragma unroll
            for (int mt = 0; mt < 2; mt++)
#pragma unroll
                for (int nt = 0; nt < 4; nt++) mma16816(acc[mt][nt], af[mt], bf[nt]);
        }
        __syncthreads();
    }
    // store with bias
#pragma unroll
    for (int mt = 0; mt < 2; mt++) {
#pragma unroll
        for (int nt = 0; nt < 4; nt++) {
            int r0 = wm * 32 + mt * 16 + group;
            int c0 = wn * 32 + nt * 8 + tq * 2;
            int m0 = by * 128;
            int n0 = bx * 64;
            float* o0 = &g_Zx[(size_t)(m0 + r0) * 4096 + n0 + c0];
            o0[0] = acc[mt][nt][0] + g_bias[n0 + c0];
            o0[1] = acc[mt][nt][1] + g_bias[n0 + c0 + 1];
            float* o1 = &g_Zx[(size_t)(m0 + r0 + 8) * 4096 + n0 + c0];
            o1[0] = acc[mt][nt][2] + g_bias[n0 + c0];
            o1[1] = acc[mt][nt][3] + g_bias[n0 + c0 + 1];
        }
    }
}

// ---------------- persistent recurrent kernel ----------------
// 128 CTAs x 256 threads, all co-resident. Each CTA owns a 32-wide N tile
// (gate-interleaved => 8 full hidden units j for all 128 batch rows).
// W_h tile stays in smem for all 255 steps; c stays in registers; h is
// double-buffered in gmem with one grid barrier per step.
#define SA 136                       // A chunk row stride (halfs)
#define SW 1032                      // Wh row stride (halfs)
#define SM_WH_BYTES (32 * SW * 2)            // 66048
#define SM_AB_BYTES (128 * SA * 2)           // 34816 per buffer
#define SM_ZB_OFF (SM_WH_BYTES + 2 * SM_AB_BYTES)    // 135680
#define SM_TOTAL (SM_ZB_OFF + 128 * 36 * 4)          // 154112

__device__ __forceinline__ void grid_bar(int phase) {
    __threadfence();
    __syncthreads();
    if (threadIdx.x == 0) {
        atomicAdd(&g_bar, 1u);
        unsigned target = (unsigned)NCTA * (unsigned)phase;
        unsigned v;
        do {
            asm volatile("ld.acquire.gpu.u32 %0, [%1];" : "=r"(v) : "l"(&g_bar) : "memory");
            if (v < target) __nanosleep(64);
        } while (v < target);
    }
    __syncthreads();
    __threadfence();
}

__global__ void __launch_bounds__(256, 1) lstm_persist_kernel(float* __restrict__ out) {
    extern __shared__ char sm[];
    __half* Wh_s = (__half*)sm;
    __half* As = (__half*)(sm + SM_WH_BYTES);
    float* zbuf = (float*)(sm + SM_ZB_OFF);

    const int bx = blockIdx.x;
    const int tid = threadIdx.x;
    const int warp = tid >> 5, lane = tid & 31;
    const int wm = warp & 3, wn = warp >> 2;
    const int group = lane >> 2, tq = lane & 3;

    uint32_t wh_u = (uint32_t)__cvta_generic_to_shared(Wh_s);
    uint32_t as_u = (uint32_t)__cvta_generic_to_shared(As);

    // ---- load Wh tile (32 x 1024 fp16) into smem once ----
    {
        const __half* Bg = g_Wh + (size_t)bx * 32 * 1024;
#pragma unroll
        for (int i = 0; i < 16; i++) {
            int idx = tid + i * 256;           // 0..4095, 16B units
            int r = idx >> 7, c = idx & 127;
            *(uint4*)&Wh_s[r * SW + c * 8] = *(const uint4*)&Bg[r * 1024 + c * 8];
        }
    }

    // ---- per-thread (b, j) ownership for gate phase; c in registers ----
    int ci[4];
    float c_reg[4];
#pragma unroll
    for (int i = 0; i < 4; i++) {
        int p = tid + i * 256;                 // 0..1023
        int b = p >> 3, jl = p & 7;
        ci[i] = b * 1024 + bx * 8 + jl;
        c_reg[i] = 0.0f;
        g_h2[ci[i]] = __float2half(0.0f);      // zero h buffer 0 (this CTA's slice)
        out[ci[i]] = 0.0f;                     // out[0] = h0 = zeros
    }

    // ldmatrix byte offsets
    uint32_t a_off[2], b_off;
#pragma unroll
    for (int mt = 0; mt < 2; mt++)
        a_off[mt] = as_u + ((wm * 32 + mt * 16 + (lane & 15)) * SA + ((lane >> 4) << 3)) * 2;
    {
        int m = lane >> 3;
        b_off = wh_u + ((wn * 16 + ((m >> 1) << 3) + (lane & 7)) * SW + ((m & 1) << 3)) * 2;
    }

    grid_bar(1);                               // all slices of h[0] visible

    for (int t = 1; t < TT; t++) {
        const __half* hr = g_h2 + (size_t)((t - 1) & 1) * BB * HH;
        __half* hw = g_h2 + (size_t)(t & 1) * BB * HH;

        // prefetch chunk 0
#pragma unroll
        for (int i = 0; i < 8; i++) {
            int idx = tid + i * 256;           // 0..2047
            int r = idx >> 4, c = idx & 15;
            cpasync16(as_u + (r * SA + c * 8) * 2, &hr[r * 1024 + c * 8]);
        }
        cp_commit();

        float acc[2][2][4];
#pragma unroll
        for (int mt = 0; mt < 2; mt++)
#pragma unroll
            for (int nt = 0; nt < 2; nt++)
#pragma unroll
                for (int e = 0; e < 4; e++) acc[mt][nt][e] = 0.0f;

#pragma unroll 1
        for (int kc = 0; kc < 8; kc++) {
            if (kc < 7) {
                uint32_t dst = as_u + (((kc + 1) & 1) ? SM_AB_BYTES : 0);
#pragma unroll
                for (int i = 0; i < 8; i++) {
                    int idx = tid + i * 256;
                    int r = idx >> 4, c = idx & 15;
                    cpasync16(dst + (r * SA + c * 8) * 2, &hr[r * 1024 + (kc + 1) * 128 + c * 8]);
                }
                cp_commit();
                cp_wait<1>();
            } else {
                cp_wait<0>();
            }
            __syncthreads();

            uint32_t abuf = as_u + ((kc & 1) ? SM_AB_BYTES : 0) - as_u;  // 0 or SM_AB_BYTES
            uint32_t kcol = (uint32_t)kc * 128u;
#pragma unroll
            for (int kk = 0; kk < 128; kk += 16) {
                uint32_t af[2][4], bf[2][2];
#pragma unroll
                for (int mt = 0; mt < 2; mt++)
                    ldsm_x4(af[mt][0], af[mt][1], af[mt][2], af[mt][3],
                            a_off[mt] + abuf + kk * 2);
                ldsm_x4(bf[0][0], bf[0][1], bf[1][0], bf[1][1],
                        b_off + (kcol + kk) * 2);
#pragma unroll
                for (int mt = 0; mt < 2; mt++)
#pragma unroll
                    for (int nt = 0; nt < 2; nt++) mma16816(acc[mt][nt], af[mt], bf[nt]);
            }
            __syncthreads();
        }

        // spill z tile (h.Wh part) to smem
#pragma unroll
        for (int mt = 0; mt < 2; mt++) {
#pragma unroll
            for (int nt = 0; nt < 2; nt++) {
                int r0 = wm * 32 + mt * 16 + group;
                int c0 = wn * 16 + nt * 8 + tq * 2;
                zbuf[r0 * 36 + c0] = acc[mt][nt][0];
                zbuf[r0 * 36 + c0 + 1] = acc[mt][nt][1];
                zbuf[(r0 + 8) * 36 + c0] = acc[mt][nt][2];
                zbuf[(r0 + 8) * 36 + c0 + 1] = acc[mt][nt][3];
            }
        }
        __syncthreads();

        // gates + state update: 1024 (b, j) pairs, 4 per thread
        const float* Zxt = g_Zx + (size_t)(t - 1) * BB * N4;
        float* outt = out + (size_t)t * (BB * HH);
#pragma unroll
        for (int i = 0; i < 4; i++) {
            int p = tid + i * 256;
            int b = p >> 3, jl = p & 7;
            float4 zh = *(const float4*)&zbuf[b * 36 + jl * 4];
            float4 zx = *(const float4*)&Zxt[(size_t)b * 4096 + bx * 32 + jl * 4];
            float gg = tanhf(zh.x + zx.x);
            float ii = sigmoidf_(zh.y + zx.y);
            float ff = sigmoidf_(zh.z + zx.z);
            float oo = sigmoidf_(zh.w + zx.w);
            float cn = ff * c_reg[i] + ii * gg;
            float hn = oo * tanhf(cn);
            c_reg[i] = cn;
            outt[ci[i]] = hn;
            hw[ci[i]] = __float2half(hn);
        }

        grid_bar(t + 1);                       // publish h for next step
    }
}

// ---------------- launch ----------------
extern "C" void kernel_launch(void* const* d_in, const int* in_sizes, int n_in,
                              void* d_out, int out_size) {
    const float* embeds = (const float*)d_in[0];
    const float* Wg = (const float*)d_in[1];
    const float* Wi = (const float*)d_in[2];
    const float* Wf = (const float*)d_in[3];
    const float* Wo = (const float*)d_in[4];
    const float* bg = (const float*)d_in[5];
    const float* bi = (const float*)d_in[6];
    const float* bf = (const float*)d_in[7];
    const float* bo = (const float*)d_in[8];
    float* out = (float*)d_out;

    cudaFuncSetAttribute(lstm_persist_kernel,
                         cudaFuncAttributeMaxDynamicSharedMemorySize, SM_TOTAL);

    init_kernel<<<1, 32>>>();
    convw_kernel<<<(N4 * 1024 + 255) / 256, 256>>>(Wg, Wi, Wf, Wo, bg, bi, bf, bo);
    convx_kernel<<<((TT - 1) * BB * EE + 255) / 256, 256>>>(embeds);

    dim3 gx(64, TT - 1);
    xgemm_kernel<<<gx, 256>>>();

    lstm_persist_kernel<<<NCTA, 256, SM_TOTAL>>>(out);
}

// round 4
// speedup vs baseline: 1.9119x; 1.1996x over previous
#include <cuda_runtime.h>
#include <cuda_fp16.h>
#include <cstdint>

// Problem dims
#define TT 256
#define BB 128
#define EE 1024
#define HH 1024
#define N4 4096   // 4*H, gate-interleaved: n' = j*4 + gate  (0=g,1=i,2=f,3=o)
#define NCTA 128  // persistent kernel CTAs (all co-resident: 128 <= 148 SMs)

// ---------------- device scratch (allocation-free: __device__ globals) ----------------
__device__ __half g_Wx[N4 * EE];                       // 8 MB   W[:, :E]  reordered
__device__ __half g_Wh[N4 * HH];                       // 8 MB   W[:, E:]  reordered
__device__ float  g_bias[N4];                          // reordered bias
__device__ __half g_X16[(TT - 1) * BB * EE];           // 66.8 MB, embeds[1:] fp16
__device__ float  g_Zx[(TT - 1) * BB * N4];            // 535 MB, x-part preactivations (+bias)
__device__ __half g_h2[2 * BB * HH];                   // double-buffered h (fp16)
__device__ unsigned g_bar;                             // grid barrier counter

// ---------------- helpers ----------------
__device__ __forceinline__ void mma16816(float* d, const uint32_t* a, const uint32_t* b) {
    asm volatile(
        "mma.sync.aligned.m16n8k16.row.col.f32.f16.f16.f32 "
        "{%0,%1,%2,%3}, {%4,%5,%6,%7}, {%8,%9}, {%0,%1,%2,%3};\n"
        : "+f"(d[0]), "+f"(d[1]), "+f"(d[2]), "+f"(d[3])
        : "r"(a[0]), "r"(a[1]), "r"(a[2]), "r"(a[3]), "r"(b[0]), "r"(b[1]));
}

__device__ __forceinline__ void ldsm_x4(uint32_t& r0, uint32_t& r1, uint32_t& r2, uint32_t& r3,
                                        uint32_t addr) {
    asm volatile("ldmatrix.sync.aligned.m8n8.x4.shared.b16 {%0,%1,%2,%3}, [%4];\n"
                 : "=r"(r0), "=r"(r1), "=r"(r2), "=r"(r3) : "r"(addr));
}

__device__ __forceinline__ void cpasync16(uint32_t saddr, const void* g) {
    asm volatile("cp.async.cg.shared.global [%0], [%1], 16;\n" :: "r"(saddr), "l"(g));
}
__device__ __forceinline__ void cp_commit() { asm volatile("cp.async.commit_group;\n"); }
template <int N>
__device__ __forceinline__ void cp_wait() { asm volatile("cp.async.wait_group %0;\n" :: "n"(N)); }

__device__ __forceinline__ float sigmoidf_(float x) { return 1.0f / (1.0f + expf(-x)); }

// ---------------- conversion / init kernels ----------------
__global__ void convw_kernel(const float* __restrict__ Wg, const float* __restrict__ Wi,
                             const float* __restrict__ Wf, const float* __restrict__ Wo,
                             const float* __restrict__ bg, const float* __restrict__ bi,
                             const float* __restrict__ bf, const float* __restrict__ bo) {
    int idx = blockIdx.x * 256 + threadIdx.x;            // over N4*1024
    if (idx >= N4 * 1024) return;
    int np = idx >> 10, k = idx & 1023;
    int j = np >> 2, gate = np & 3;
    const float* W = (gate == 0) ? Wg : (gate == 1) ? Wi : (gate == 2) ? Wf : Wo;
    g_Wx[idx] = __float2half(W[j * 2048 + k]);
    g_Wh[idx] = __float2half(W[j * 2048 + 1024 + k]);
    if (k == 0) {
        const float* bs = (gate == 0) ? bg : (gate == 1) ? bi : (gate == 2) ? bf : bo;
        g_bias[np] = bs[j];
    }
}

__global__ void convx_kernel(const float* __restrict__ embeds) {
    int i = blockIdx.x * 256 + threadIdx.x;
    if (i < (TT - 1) * BB * EE) g_X16[i] = __float2half(embeds[i + BB * EE]);
}

__global__ void init_kernel() {
    if (threadIdx.x == 0) g_bar = 0u;                    // reset barrier per graph replay
}

// ---------------- x-GEMM: Zx[m][n'] = bias[n'] + X[m] . Wx[n'] ----------------
// BM=128, BN=64, BK=64; 256 threads; 8 warps as 4(M) x 2(N); warp tile 32x32.
// 2-stage cp.async double buffer: load k0+1 overlapped with compute k0.
#define XG_STAGE 27648                   // (128+64)*72*2 bytes per stage
#define XG_BOFF  18432                   // B offset within stage (128*72*2)
#define XG_SMEM  (2 * XG_STAGE)          // 55296

__global__ void __launch_bounds__(256) xgemm_kernel() {
    extern __shared__ char xsm[];
    const int bx = blockIdx.x;                 // n tile (64 tiles of 64)
    const int by = blockIdx.y;                 // m tile (255 tiles of 128)
    const int tid = threadIdx.x;
    const int warp = tid >> 5, lane = tid & 31;
    const int wm = warp & 3, wn = warp >> 2;
    const int group = lane >> 2, tq = lane & 3;

    const __half* Ag = g_X16 + (size_t)by * 128 * 1024;
    const __half* Bg = g_Wx + (size_t)bx * 64 * 1024;

    uint32_t base_u = (uint32_t)__cvta_generic_to_shared(xsm);

    // ldmatrix byte offsets relative to stage base
    uint32_t a_rel[2], b_rel[2];
#pragma unroll
    for (int mt = 0; mt < 2; mt++)
        a_rel[mt] = ((wm * 32 + mt * 16 + (lane & 15)) * 72 + ((lane >> 4) << 3)) * 2;
    {
        int m = lane >> 3;
#pragma unroll
        for (int p = 0; p < 2; p++)
            b_rel[p] = XG_BOFF + ((wn * 32 + p * 16 + ((m >> 1) << 3) + (lane & 7)) * 72 +
                                  ((m & 1) << 3)) * 2;
    }

    // per-thread load coords
    const int ra = tid >> 3, ca = tid & 7;

    float acc[2][4][4];
#pragma unroll
    for (int mt = 0; mt < 2; mt++)
#pragma unroll
        for (int nt = 0; nt < 4; nt++)
#pragma unroll
            for (int e = 0; e < 4; e++) acc[mt][nt][e] = 0.0f;

    // issue stage 0
    {
        uint32_t sa = base_u, sb = base_u + XG_BOFF;
#pragma unroll
        for (int i = 0; i < 4; i++) {
            int r = ra + i * 32;
            cpasync16(sa + (r * 72 + ca * 8) * 2, &Ag[(size_t)r * 1024 + ca * 8]);
        }
#pragma unroll
        for (int i = 0; i < 2; i++) {
            int r = ra + i * 32;
            cpasync16(sb + (r * 72 + ca * 8) * 2, &Bg[(size_t)r * 1024 + ca * 8]);
        }
        cp_commit();
    }

#pragma unroll 1
    for (int it = 0; it < 16; it++) {
        if (it < 15) {                         // issue next stage
            int k0 = (it + 1) * 64;
            uint32_t sa = base_u + ((it + 1) & 1) * XG_STAGE;
            uint32_t sb = sa + XG_BOFF;
#pragma unroll
            for (int i = 0; i < 4; i++) {
                int r = ra + i * 32;
                cpasync16(sa + (r * 72 + ca * 8) * 2, &Ag[(size_t)r * 1024 + k0 + ca * 8]);
            }
#pragma unroll
            for (int i = 0; i < 2; i++) {
                int r = ra + i * 32;
                cpasync16(sb + (r * 72 + ca * 8) * 2, &Bg[(size_t)r * 1024 + k0 + ca * 8]);
            }
            cp_commit();
            cp_wait<1>();
        } else {
            cp_wait<0>();
        }
        __syncthreads();

        uint32_t stg = base_u + (it & 1) * XG_STAGE;
#pragma unroll
        for (int kk = 0; kk < 64; kk += 16) {
            uint32_t af[2][4], bf[4][2];
#pragma unroll
            for (int mt = 0; mt < 2; mt++)
                ldsm_x4(af[mt][0], af[mt][1], af[mt][2], af[mt][3], stg + a_rel[mt] + kk * 2);
#pragma unroll
            for (int p = 0; p < 2; p++)
                ldsm_x4(bf[2 * p][0], bf[2 * p][1], bf[2 * p + 1][0], bf[2 * p + 1][1],
                        stg + b_rel[p] + kk * 2);
#pragma unroll
            for (int mt = 0; mt < 2; mt++)
#pragma unroll
                for (int nt = 0; nt < 4; nt++) mma16816(acc[mt][nt], af[mt], bf[nt]);
        }
        __syncthreads();                       // protect stage before re-fill
    }

    // store with bias
#pragma unroll
    for (int mt = 0; mt < 2; mt++) {
#pragma unroll
        for (int nt = 0; nt < 4; nt++) {
            int r0 = wm * 32 + mt * 16 + group;
            int c0 = wn * 32 + nt * 8 + tq * 2;
            int m0 = by * 128;
            int n0 = bx * 64;
            float* o0 = &g_Zx[(size_t)(m0 + r0) * 4096 + n0 + c0];
            o0[0] = acc[mt][nt][0] + g_bias[n0 + c0];
            o0[1] = acc[mt][nt][1] + g_bias[n0 + c0 + 1];
            float* o1 = &g_Zx[(size_t)(m0 + r0 + 8) * 4096 + n0 + c0];
            o1[0] = acc[mt][nt][2] + g_bias[n0 + c0];
            o1[1] = acc[mt][nt][3] + g_bias[n0 + c0 + 1];
        }
    }
}

// ---------------- persistent recurrent kernel ----------------
// 128 CTAs x 256 threads, all co-resident. Each CTA owns a 32-wide N tile.
// W_h tile resident in smem; c in registers; h double-buffered in gmem with
// one grid barrier per step. 3-deep cp.async chunk pipeline for h loads;
// Zx slice prefetched into smem at step start (hidden behind the GEMM).
#define SA 136                                // A chunk row stride (halfs)
#define SW 1032                               // Wh row stride (halfs)
#define SM_WH_BYTES (32 * SW * 2)             // 66048
#define SM_AB_BYTES (128 * SA * 2)            // 34816 per buffer
#define SM_ZX_OFF (SM_WH_BYTES + 3 * SM_AB_BYTES)       // 170496
#define SM_ZB_OFF (SM_ZX_OFF + 1024 * 16)               // 186880
#define SM_TOTAL (SM_ZB_OFF + 128 * 36 * 4)             // 205312

__device__ __forceinline__ void grid_bar(int phase) {
    __threadfence();
    __syncthreads();
    if (threadIdx.x == 0) {
        atomicAdd(&g_bar, 1u);
        unsigned target = (unsigned)NCTA * (unsigned)phase;
        unsigned v;
        int spins = 0;
        do {
            asm volatile("ld.acquire.gpu.u32 %0, [%1];" : "=r"(v) : "l"(&g_bar) : "memory");
            if (v < target) {
                __nanosleep(spins < 8 ? 32 : 128);
                spins++;
            }
        } while (v < target);
    }
    __syncthreads();
    __threadfence();
}

__global__ void __launch_bounds__(256, 1) lstm_persist_kernel(float* __restrict__ out) {
    extern __shared__ char sm[];
    __half* Wh_s = (__half*)sm;
    float* zxs = (float*)(sm + SM_ZX_OFF);
    float* zbuf = (float*)(sm + SM_ZB_OFF);

    const int bx = blockIdx.x;
    const int tid = threadIdx.x;
    const int warp = tid >> 5, lane = tid & 31;
    const int wm = warp & 3, wn = warp >> 2;
    const int group = lane >> 2, tq = lane & 3;

    uint32_t wh_u = (uint32_t)__cvta_generic_to_shared(Wh_s);
    uint32_t ab_u = (uint32_t)__cvta_generic_to_shared(sm + SM_WH_BYTES);
    uint32_t zx_u = (uint32_t)__cvta_generic_to_shared(zxs);

    // ---- load Wh tile (32 x 1024 fp16) into smem once ----
    {
        const __half* Bg = g_Wh + (size_t)bx * 32 * 1024;
#pragma unroll
        for (int i = 0; i < 16; i++) {
            int idx = tid + i * 256;           // 0..4095, 16B units
            int r = idx >> 7, c = idx & 127;
            *(uint4*)&Wh_s[r * SW + c * 8] = *(const uint4*)&Bg[r * 1024 + c * 8];
        }
    }

    // ---- per-thread (b, j) ownership for gate phase; c in registers ----
    int ci[4];
    float c_reg[4];
#pragma unroll
    for (int i = 0; i < 4; i++) {
        int p = tid + i * 256;                 // 0..1023
        int b = p >> 3, jl = p & 7;
        ci[i] = b * 1024 + bx * 8 + jl;
        c_reg[i] = 0.0f;
        g_h2[ci[i]] = __float2half(0.0f);      // zero h buffer 0 (this CTA's slice)
        out[ci[i]] = 0.0f;                     // out[0] = h0 = zeros
    }

    // ldmatrix byte offsets
    uint32_t a_rel[2], b_off;
#pragma unroll
    for (int mt = 0; mt < 2; mt++)
        a_rel[mt] = ((wm * 32 + mt * 16 + (lane & 15)) * SA + ((lane >> 4) << 3)) * 2;
    {
        int m = lane >> 3;
        b_off = wh_u + ((wn * 16 + ((m >> 1) << 3) + (lane & 7)) * SW + ((m & 1) << 3)) * 2;
    }

    const int rh = tid >> 4, ch = tid & 15;    // h-chunk load coords

    grid_bar(1);                               // all slices of h[0] visible

#pragma unroll 1
    for (int t = 1; t < TT; t++) {
        const __half* hr = g_h2 + (size_t)((t - 1) & 1) * BB * HH;
        __half* hw = g_h2 + (size_t)(t & 1) * BB * HH;
        const float* Zxt = g_Zx + (size_t)(t - 1) * BB * N4;

        // group 0: chunk 0 + zx slice
        {
            uint32_t dst = ab_u;
#pragma unroll
            for (int i = 0; i < 8; i++) {
                int r = rh + i * 16;
                cpasync16(dst + (r * SA + ch * 8) * 2, &hr[(size_t)r * 1024 + ch * 8]);
            }
#pragma unroll
            for (int i = 0; i < 4; i++) {
                int p = tid + i * 256;
                int b = p >> 3, jl = p & 7;
                cpasync16(zx_u + p * 16, &Zxt[(size_t)b * 4096 + bx * 32 + jl * 4]);
            }
            cp_commit();
        }
        // groups 1, 2: chunks 1, 2
#pragma unroll
        for (int kc = 1; kc < 3; kc++) {
            uint32_t dst = ab_u + kc * SM_AB_BYTES;
#pragma unroll
            for (int i = 0; i < 8; i++) {
                int r = rh + i * 16;
                cpasync16(dst + (r * SA + ch * 8) * 2,
                          &hr[(size_t)r * 1024 + kc * 128 + ch * 8]);
            }
            cp_commit();
        }

        float acc[2][2][4];
#pragma unroll
        for (int mt = 0; mt < 2; mt++)
#pragma unroll
            for (int nt = 0; nt < 2; nt++)
#pragma unroll
                for (int e = 0; e < 4; e++) acc[mt][nt][e] = 0.0f;

#pragma unroll 1
        for (int kc = 0; kc < 8; kc++) {
            // need chunk kc's group complete
            if (kc <= 5)      cp_wait<2>();
            else if (kc == 6) cp_wait<1>();
            else              cp_wait<0>();
            __syncthreads();

            uint32_t abuf = ab_u + (uint32_t)(kc % 3) * SM_AB_BYTES;
            uint32_t kcol = (uint32_t)kc * 128u;
#pragma unroll
            for (int kk = 0; kk < 128; kk += 16) {
                uint32_t af[2][4], bf[2][2];
#pragma unroll
                for (int mt = 0; mt < 2; mt++)
                    ldsm_x4(af[mt][0], af[mt][1], af[mt][2], af[mt][3],
                            abuf + a_rel[mt] + kk * 2);
                ldsm_x4(bf[0][0], bf[0][1], bf[1][0], bf[1][1],
                        b_off + (kcol + kk) * 2);
#pragma unroll
                for (int mt = 0; mt < 2; mt++)
#pragma unroll
                    for (int nt = 0; nt < 2; nt++) mma16816(acc[mt][nt], af[mt], bf[nt]);
            }
            __syncthreads();                   // buffer will be re-filled below

            if (kc + 3 < 8) {                  // issue chunk kc+3 into buf (kc+3)%3
                uint32_t dst = ab_u + (uint32_t)((kc + 3) % 3) * SM_AB_BYTES;
#pragma unroll
                for (int i = 0; i < 8; i++) {
                    int r = rh + i * 16;
                    cpasync16(dst + (r * SA + ch * 8) * 2,
                              &hr[(size_t)r * 1024 + (kc + 3) * 128 + ch * 8]);
                }
                cp_commit();
            }
        }

        // spill z tile (h.Wh part) to smem
#pragma unroll
        for (int mt = 0; mt < 2; mt++) {
#pragma unroll
            for (int nt = 0; nt < 2; nt++) {
                int r0 = wm * 32 + mt * 16 + group;
                int c0 = wn * 16 + nt * 8 + tq * 2;
                zbuf[r0 * 36 + c0] = acc[mt][nt][0];
                zbuf[r0 * 36 + c0 + 1] = acc[mt][nt][1];
                zbuf[(r0 + 8) * 36 + c0] = acc[mt][nt][2];
                zbuf[(r0 + 8) * 36 + c0 + 1] = acc[mt][nt][3];
            }
        }
        __syncthreads();

        // gates + state update: 1024 (b, j) pairs, 4 per thread; zx from smem
        float* outt = out + (size_t)t * (BB * HH);
#pragma unroll
        for (int i = 0; i < 4; i++) {
            int p = tid + i * 256;
            int b = p >> 3, jl = p & 7;
            float4 zh = *(const float4*)&zbuf[b * 36 + jl * 4];
            float4 zx = *(const float4*)&zxs[p * 4];
            float gg = tanhf(zh.x + zx.x);
            float ii = sigmoidf_(zh.y + zx.y);
            float ff = sigmoidf_(zh.z + zx.z);
            float oo = sigmoidf_(zh.w + zx.w);
            float cn = ff * c_reg[i] + ii * gg;
            float hn = oo * tanhf(cn);
            c_reg[i] = cn;
            outt[ci[i]] = hn;
            hw[ci[i]] = __float2half(hn);
        }

        grid_bar(t + 1);                       // publish h for next step
    }
}

// ---------------- launch ----------------
extern "C" void kernel_launch(void* const* d_in, const int* in_sizes, int n_in,
                              void* d_out, int out_size) {
    const float* embeds = (const float*)d_in[0];
    const float* Wg = (const float*)d_in[1];
    const float* Wi = (const float*)d_in[2];
    const float* Wf = (const float*)d_in[3];
    const float* Wo = (const float*)d_in[4];
    const float* bg = (const float*)d_in[5];
    const float* bi = (const float*)d_in[6];
    const float* bf = (const float*)d_in[7];
    const float* bo = (const float*)d_in[8];
    float* out = (float*)d_out;

    cudaFuncSetAttribute(xgemm_kernel,
                         cudaFuncAttributeMaxDynamicSharedMemorySize, XG_SMEM);
    cudaFuncSetAttribute(lstm_persist_kernel,
                         cudaFuncAttributeMaxDynamicSharedMemorySize, SM_TOTAL);

    init_kernel<<<1, 32>>>();
    convw_kernel<<<(N4 * 1024 + 255) / 256, 256>>>(Wg, Wi, Wf, Wo, bg, bi, bf, bo);
    convx_kernel<<<((TT - 1) * BB * EE + 255) / 256, 256>>>(embeds);

    dim3 gx(64, TT - 1);
    xgemm_kernel<<<gx, 256, XG_SMEM>>>();

    lstm_persist_kernel<<<NCTA, 256, SM_TOTAL>>>(out);
}